// round 5
// baseline (speedup 1.0000x reference)
#include <cuda_runtime.h>
#include <cuda_bf16.h>
#include <cstdint>

#define B_  1024
#define D_  512
#define V_  100000

constexpr float MARGIN_COS = 0.9210609940028851f;  // cos(0.4)
constexpr float MARGIN_SIN = 0.3894183423086505f;  // sin(0.4)
constexpr float EPS_CLIP   = 1e-7f;

// ---- scratch (device globals: allocation-free per harness rules) ----
__device__ __align__(128) __nv_bfloat16 g_x16[B_ * D_];
__device__ __align__(128) __nv_bfloat16 g_w16[(size_t)D_ * V_];
__device__ float g_inv_x[B_];
__device__ float g_inv_w[V_];
__device__ float g_sumexp[B_];
__device__ float g_label_logit[B_];
__device__ int   g_labels[B_];

// ============================================================
// labels dtype detection (int64 vs int32) + normalization
// ============================================================
__global__ void k_labels(const int* __restrict__ raw) {
    __shared__ int nonzero;
    int t = threadIdx.x;  // 1024
    if (t == 0) nonzero = 0;
    __syncthreads();
    if (t < 512) {
        if (raw[2 * t + 1] != 0) atomicOr(&nonzero, 1);
    }
    __syncthreads();
    bool is64 = (nonzero == 0);
    g_labels[t] = is64 ? raw[2 * t] : raw[t];
}

// ============================================================
// x prep: bf16 convert + row inv-norms; zero g_sumexp
// ============================================================
__global__ void k_prep_x(const float* __restrict__ x) {
    int b = blockIdx.x;
    int t = threadIdx.x;  // 128
    float ss = 0.f;
#pragma unroll
    for (int i = 0; i < 4; i++) {
        int k = t + i * 128;
        float v = x[b * D_ + k];
        ss += v * v;
        g_x16[b * D_ + k] = __float2bfloat16(v);
    }
#pragma unroll
    for (int o = 16; o; o >>= 1) ss += __shfl_xor_sync(0xffffffffu, ss, o);
    __shared__ float ws[4];
    if ((t & 31) == 0) ws[t >> 5] = ss;
    __syncthreads();
    if (t == 0) {
        float s = ws[0] + ws[1] + ws[2] + ws[3];
        g_inv_x[b]  = 1.0f / fmaxf(sqrtf(s), 1e-12f);
        g_sumexp[b] = 0.f;
    }
}

// ============================================================
// w prep: bf16 convert + column inv-norms (one pass, coalesced)
// ============================================================
__global__ void k_prep_w(const float* __restrict__ w) {
    int v = blockIdx.x * 256 + threadIdx.x;
    if (v >= V_) return;
    float ss = 0.f;
    size_t idx = (size_t)v;
#pragma unroll 8
    for (int d = 0; d < D_; d++) {
        float val = w[idx];
        ss += val * val;
        g_w16[idx] = __float2bfloat16(val);
        idx += V_;
    }
    g_inv_w[v] = 1.0f / fmaxf(sqrtf(ss), 1e-12f);
}

// ============================================================
// GEMM + fused ArcFace epilogue
// CTA: BM=128 x BN=128, BK=32, 128 threads (2x2 warp grid, 64x64/warp)
// 3-stage cp.async ring; mma.sync m16n8k16 bf16
// ============================================================
#define BM 128
#define BN 128
#define BK 32
#define STAGES 3
#define A_PITCH 40    // 32 + 8 pad (80B rows; conflict-free ldmatrix)
#define B_PITCH 136   // 128 + 8 pad (272B rows; conflict-free ldmatrix)
#define A_STAGE (BM * A_PITCH)          // bf16 elems
#define B_STAGE (BK * B_PITCH)
#define SMEM_DYN ((A_STAGE + B_STAGE) * STAGES * 2)  // bytes = 56832

__device__ __forceinline__ void cp_async16(uint32_t smem, const void* gmem, int sz) {
    asm volatile("cp.async.cg.shared.global [%0], [%1], 16, %2;\n"
                 :: "r"(smem), "l"(gmem), "r"(sz) : "memory");
}
__device__ __forceinline__ void ldsm_x4(uint32_t& r0, uint32_t& r1, uint32_t& r2, uint32_t& r3, uint32_t addr) {
    asm volatile("ldmatrix.sync.aligned.m8n8.x4.shared.b16 {%0,%1,%2,%3}, [%4];\n"
                 : "=r"(r0), "=r"(r1), "=r"(r2), "=r"(r3) : "r"(addr));
}
__device__ __forceinline__ void ldsm_x4_t(uint32_t& r0, uint32_t& r1, uint32_t& r2, uint32_t& r3, uint32_t addr) {
    asm volatile("ldmatrix.sync.aligned.m8n8.x4.trans.shared.b16 {%0,%1,%2,%3}, [%4];\n"
                 : "=r"(r0), "=r"(r1), "=r"(r2), "=r"(r3) : "r"(addr));
}
__device__ __forceinline__ void mma16816(float* c, const uint32_t* a, const uint32_t* b) {
    asm volatile(
        "mma.sync.aligned.m16n8k16.row.col.f32.bf16.bf16.f32 "
        "{%0,%1,%2,%3}, {%4,%5,%6,%7}, {%8,%9}, {%0,%1,%2,%3};\n"
        : "+f"(c[0]), "+f"(c[1]), "+f"(c[2]), "+f"(c[3])
        : "r"(a[0]), "r"(a[1]), "r"(a[2]), "r"(a[3]), "r"(b[0]), "r"(b[1]));
}

__global__ __launch_bounds__(128, 2) void k_gemm() {
    extern __shared__ __nv_bfloat16 smem_dyn[];
    __nv_bfloat16* As = smem_dyn;                       // STAGES * A_STAGE
    __nv_bfloat16* Bs = smem_dyn + STAGES * A_STAGE;    // STAGES * B_STAGE
    __shared__ float rowsum_sm[BM];
    __shared__ float inv_x_s[BM];
    __shared__ float inv_w_s[BN];
    __shared__ int   label_s[BM];

    const int bm = blockIdx.x;   // M-tile (fast index -> same-w CTAs adjacent for L2 reuse)
    const int bn = blockIdx.y;   // V-tile
    const int tid = threadIdx.x;
    const int warp = tid >> 5, lane = tid & 31;
    const int wm = warp & 1;     // 2 warps over M (64 rows each)
    const int wn = warp >> 1;    // 2 warps over N (64 cols each)

    const uint32_t as0 = (uint32_t)__cvta_generic_to_shared(As);
    const uint32_t bs0 = (uint32_t)__cvta_generic_to_shared(Bs);

    // 128 threads: 4 cp.async16 per operand per stage
    auto load_tiles = [&](int kt, int buf) {
#pragma unroll
        for (int i = 0; i < 4; i++) {
            int c = tid + i * 128;           // 0..511
            int row  = c >> 2;               // 0..127
            int koff = (c & 3) * 8;          // 0,8,16,24
            const __nv_bfloat16* gp = &g_x16[(bm * BM + row) * D_ + kt * BK + koff];
            cp_async16(as0 + (buf * A_STAGE + row * A_PITCH + koff) * 2, gp, 16);
        }
#pragma unroll
        for (int i = 0; i < 4; i++) {
            int c = tid + i * 128;
            int drow = c >> 4;               // 0..31
            int voff = (c & 15) * 8;         // 0..120
            int v = bn * BN + voff;
            const __nv_bfloat16* gp = &g_w16[(size_t)(kt * BK + drow) * V_ + v];
            cp_async16(bs0 + (buf * B_STAGE + drow * B_PITCH + voff) * 2, gp, (v < V_) ? 16 : 0);
        }
        asm volatile("cp.async.commit_group;\n" ::: "memory");
    };

    load_tiles(0, 0);
    load_tiles(1, 1);

    if (tid < BM) {
        inv_x_s[tid]   = g_inv_x[bm * BM + tid];
        label_s[tid]   = g_labels[bm * BM + tid];
        int v = bn * BN + tid;
        inv_w_s[tid]   = (v < V_) ? g_inv_w[v] : 0.f;
        rowsum_sm[tid] = 0.f;
    }

    float acc[4][8][4];
#pragma unroll
    for (int mf = 0; mf < 4; mf++)
#pragma unroll
        for (int nf = 0; nf < 8; nf++)
#pragma unroll
            for (int j = 0; j < 4; j++) acc[mf][nf][j] = 0.f;

    const int KT = D_ / BK;  // 16
    for (int kt = 0; kt < KT; kt++) {
        asm volatile("cp.async.wait_group 1;\n" ::: "memory");
        __syncthreads();
        // prefetch kt+2 into the stage freed last iteration
        if (kt + 2 < KT) load_tiles(kt + 2, (kt + 2) % STAGES);
        else asm volatile("cp.async.commit_group;\n" ::: "memory");  // keep group count uniform

        int buf = kt % STAGES;
        uint32_t abase = as0 + buf * (A_STAGE * 2);
        uint32_t bbase = bs0 + buf * (B_STAGE * 2);

#pragma unroll
        for (int ks = 0; ks < 2; ks++) {
            uint32_t a[4][4];
#pragma unroll
            for (int mf = 0; mf < 4; mf++) {
                int row = wm * 64 + mf * 16 + (lane & 15);
                int col = ks * 16 + (lane >> 4) * 8;
                ldsm_x4(a[mf][0], a[mf][1], a[mf][2], a[mf][3],
                        abase + (row * A_PITCH + col) * 2);
            }
            uint32_t b[8][2];
#pragma unroll
            for (int ng = 0; ng < 4; ng++) {
                int krow = ks * 16 + (lane & 15);
                int ncol = wn * 64 + ng * 16 + (lane >> 4) * 8;
                uint32_t r0, r1, r2, r3;
                ldsm_x4_t(r0, r1, r2, r3, bbase + (krow * B_PITCH + ncol) * 2);
                b[ng * 2][0] = r0;      b[ng * 2][1] = r1;      // n 0..7 of group
                b[ng * 2 + 1][0] = r2;  b[ng * 2 + 1][1] = r3;  // n 8..15
            }
#pragma unroll
            for (int mf = 0; mf < 4; mf++)
#pragma unroll
                for (int nf = 0; nf < 8; nf++)
                    mma16816(acc[mf][nf], a[mf], b[nf]);
        }
    }
    __syncthreads();  // all compute done; rowsum_sm zeros visible

    // ---- fused ArcFace epilogue ----
#pragma unroll
    for (int mf = 0; mf < 4; mf++) {
        float rs0 = 0.f, rs1 = 0.f;
        int r0 = wm * 64 + mf * 16 + (lane >> 2);
        int r1 = r0 + 8;
#pragma unroll
        for (int nf = 0; nf < 8; nf++) {
            int cbase = wn * 64 + nf * 8 + (lane & 3) * 2;
#pragma unroll
            for (int j = 0; j < 2; j++) {
                int cc = cbase + j;
                int v = bn * BN + cc;
                if (v < V_) {
                    {
                        float cv = acc[mf][nf][j] * inv_x_s[r0] * inv_w_s[cc];
                        cv = fminf(fmaxf(cv, -1.f + EPS_CLIP), 1.f - EPS_CLIP);
                        float lg;
                        if (label_s[r0] == v) {
                            float s = sqrtf(fmaxf(1.f - cv * cv, 0.f));
                            lg = cv * MARGIN_COS - s * MARGIN_SIN;
                            g_label_logit[bm * BM + r0] = lg;
                        } else lg = cv;
                        rs0 += __expf(lg);
                    }
                    {
                        float cv = acc[mf][nf][2 + j] * inv_x_s[r1] * inv_w_s[cc];
                        cv = fminf(fmaxf(cv, -1.f + EPS_CLIP), 1.f - EPS_CLIP);
                        float lg;
                        if (label_s[r1] == v) {
                            float s = sqrtf(fmaxf(1.f - cv * cv, 0.f));
                            lg = cv * MARGIN_COS - s * MARGIN_SIN;
                            g_label_logit[bm * BM + r1] = lg;
                        } else lg = cv;
                        rs1 += __expf(lg);
                    }
                }
            }
        }
        rs0 += __shfl_xor_sync(0xffffffffu, rs0, 1);
        rs0 += __shfl_xor_sync(0xffffffffu, rs0, 2);
        rs1 += __shfl_xor_sync(0xffffffffu, rs1, 1);
        rs1 += __shfl_xor_sync(0xffffffffu, rs1, 2);
        if ((lane & 3) == 0) {
            atomicAdd(&rowsum_sm[r0], rs0);
            atomicAdd(&rowsum_sm[r1], rs1);
        }
    }
    __syncthreads();
    if (tid < BM) atomicAdd(&g_sumexp[bm * BM + tid], rowsum_sm[tid]);
}

// ============================================================
// final: loss = mean_b( log(sumexp[b]) - label_logit[b] )
// ============================================================
__global__ void k_final(float* __restrict__ out) {
    int t = threadIdx.x;  // 1024
    float v = logf(g_sumexp[t]) - g_label_logit[t];
#pragma unroll
    for (int o = 16; o; o >>= 1) v += __shfl_xor_sync(0xffffffffu, v, o);
    __shared__ float ws[32];
    if ((t & 31) == 0) ws[t >> 5] = v;
    __syncthreads();
    if (t < 32) {
        float s = ws[t];
#pragma unroll
        for (int o = 16; o; o >>= 1) s += __shfl_xor_sync(0xffffffffu, s, o);
        if (t == 0) out[0] = s * (1.0f / (float)B_);
    }
}

// ============================================================
extern "C" void kernel_launch(void* const* d_in, const int* in_sizes, int n_in,
                              void* d_out, int out_size) {
    const float* x = (const float*)d_in[0];
    const float* w = (const float*)d_in[1];
    const int*   labels_raw = (const int*)d_in[2];
    float* out = (float*)d_out;

    static bool attr_set = false;
    if (!attr_set) {
        cudaFuncSetAttribute(k_gemm, cudaFuncAttributeMaxDynamicSharedMemorySize, SMEM_DYN);
        attr_set = true;
    }

    k_labels<<<1, 1024>>>(labels_raw);
    k_prep_x<<<B_, 128>>>(x);
    k_prep_w<<<(V_ + 255) / 256, 256>>>(w);
    dim3 grid(B_ / BM, (V_ + BN - 1) / BN);  // (8, 782)
    k_gemm<<<grid, 128, SMEM_DYN>>>();
    k_final<<<1, 1024>>>(out);
}

// round 8
// speedup vs baseline: 1.0554x; 1.0554x over previous
#include <cuda_runtime.h>
#include <cuda_bf16.h>
#include <cstdint>

#define B_  1024
#define D_  512
#define V_  100000

constexpr float MARGIN_COS = 0.9210609940028851f;  // cos(0.4)
constexpr float MARGIN_SIN = 0.3894183423086505f;  // sin(0.4)
constexpr float EPS_CLIP   = 1e-7f;

// ---- scratch (device globals: allocation-free per harness rules) ----
__device__ __align__(128) __nv_bfloat16 g_x16[B_ * D_];
__device__ __align__(128) __nv_bfloat16 g_w16[(size_t)D_ * V_];
__device__ float g_inv_x[B_];
__device__ float g_inv_w[V_];
__device__ float g_sumexp[B_];
__device__ float g_label_logit[B_];
__device__ int   g_labels[B_];

// ============================================================
// labels dtype detection (int64 vs int32) + normalization
// ============================================================
__global__ void k_labels(const int* __restrict__ raw) {
    __shared__ int nonzero;
    int t = threadIdx.x;  // 1024
    if (t == 0) nonzero = 0;
    __syncthreads();
    if (t < 512) {
        if (raw[2 * t + 1] != 0) atomicOr(&nonzero, 1);
    }
    __syncthreads();
    bool is64 = (nonzero == 0);
    g_labels[t] = is64 ? raw[2 * t] : raw[t];
}

// ============================================================
// x prep: bf16 convert + row inv-norms; zero g_sumexp
// ============================================================
__global__ void k_prep_x(const float* __restrict__ x) {
    int b = blockIdx.x;
    int t = threadIdx.x;  // 128
    float ss = 0.f;
#pragma unroll
    for (int i = 0; i < 4; i++) {
        int k = t + i * 128;
        float v = x[b * D_ + k];
        ss += v * v;
        g_x16[b * D_ + k] = __float2bfloat16(v);
    }
#pragma unroll
    for (int o = 16; o; o >>= 1) ss += __shfl_xor_sync(0xffffffffu, ss, o);
    __shared__ float ws[4];
    if ((t & 31) == 0) ws[t >> 5] = ss;
    __syncthreads();
    if (t == 0) {
        float s = ws[0] + ws[1] + ws[2] + ws[3];
        g_inv_x[b]  = 1.0f / fmaxf(sqrtf(s), 1e-12f);
        g_sumexp[b] = 0.f;
    }
}

// ============================================================
// w prep: bf16 convert + column inv-norms (one pass, coalesced)
// ============================================================
__global__ void k_prep_w(const float* __restrict__ w) {
    int v = blockIdx.x * 256 + threadIdx.x;
    if (v >= V_) return;
    float ss = 0.f;
    size_t idx = (size_t)v;
#pragma unroll 8
    for (int d = 0; d < D_; d++) {
        float val = w[idx];
        ss += val * val;
        g_w16[idx] = __float2bfloat16(val);
        idx += V_;
    }
    g_inv_w[v] = 1.0f / fmaxf(sqrtf(ss), 1e-12f);
}

// ============================================================
// GEMM + fused ArcFace epilogue
// CTA: BM=128 x BN=128, BK=32, 256 threads (2x4 warp grid, 64x32/warp)
// 3-stage cp.async ring; mma.sync m16n8k16 bf16
// ============================================================
#define BM 128
#define BN 128
#define BK 32
#define STAGES 3
#define A_PITCH 40    // 32 + 8 pad (80B rows; conflict-free ldmatrix)
#define B_PITCH 136   // 128 + 8 pad (272B rows; conflict-free ldmatrix)
#define A_STAGE (BM * A_PITCH)          // bf16 elems
#define B_STAGE (BK * B_PITCH)
#define SMEM_DYN ((A_STAGE + B_STAGE) * STAGES * 2)  // bytes = 56832

__device__ __forceinline__ void cp_async16(uint32_t smem, const void* gmem, int sz) {
    asm volatile("cp.async.cg.shared.global [%0], [%1], 16, %2;\n"
                 :: "r"(smem), "l"(gmem), "r"(sz) : "memory");
}
__device__ __forceinline__ void ldsm_x4(uint32_t& r0, uint32_t& r1, uint32_t& r2, uint32_t& r3, uint32_t addr) {
    asm volatile("ldmatrix.sync.aligned.m8n8.x4.shared.b16 {%0,%1,%2,%3}, [%4];\n"
                 : "=r"(r0), "=r"(r1), "=r"(r2), "=r"(r3) : "r"(addr));
}
__device__ __forceinline__ void ldsm_x4_t(uint32_t& r0, uint32_t& r1, uint32_t& r2, uint32_t& r3, uint32_t addr) {
    asm volatile("ldmatrix.sync.aligned.m8n8.x4.trans.shared.b16 {%0,%1,%2,%3}, [%4];\n"
                 : "=r"(r0), "=r"(r1), "=r"(r2), "=r"(r3) : "r"(addr));
}
__device__ __forceinline__ void mma16816(float* c, const uint32_t* a, const uint32_t* b) {
    asm volatile(
        "mma.sync.aligned.m16n8k16.row.col.f32.bf16.bf16.f32 "
        "{%0,%1,%2,%3}, {%4,%5,%6,%7}, {%8,%9}, {%0,%1,%2,%3};\n"
        : "+f"(c[0]), "+f"(c[1]), "+f"(c[2]), "+f"(c[3])
        : "r"(a[0]), "r"(a[1]), "r"(a[2]), "r"(a[3]), "r"(b[0]), "r"(b[1]));
}

__global__ __launch_bounds__(256, 2) void k_gemm() {
    extern __shared__ __nv_bfloat16 smem_dyn[];
    __nv_bfloat16* As = smem_dyn;                       // STAGES * A_STAGE
    __nv_bfloat16* Bs = smem_dyn + STAGES * A_STAGE;    // STAGES * B_STAGE
    __shared__ float rowsum_sm[BM];
    __shared__ float inv_x_s[BM];
    __shared__ float inv_w_s[BN];
    __shared__ int   label_s[BM];

    const int bm = blockIdx.x;   // M-tile (fast index -> same-w CTAs adjacent for L2 reuse)
    const int bn = blockIdx.y;   // V-tile
    const int tid = threadIdx.x;
    const int warp = tid >> 5, lane = tid & 31;
    const int wm = warp & 1;     // 2 warps over M (64 rows each)
    const int wn = warp >> 1;    // 4 warps over N (32 cols each)

    const uint32_t as0 = (uint32_t)__cvta_generic_to_shared(As);
    const uint32_t bs0 = (uint32_t)__cvta_generic_to_shared(Bs);

    // 256 threads: 2 cp.async16 per operand per stage
    auto load_tiles = [&](int kt, int buf) {
#pragma unroll
        for (int i = 0; i < 2; i++) {
            int c = tid + i * 256;           // 0..511
            int row  = c >> 2;               // 0..127
            int koff = (c & 3) * 8;          // 0,8,16,24
            const __nv_bfloat16* gp = &g_x16[(bm * BM + row) * D_ + kt * BK + koff];
            cp_async16(as0 + (buf * A_STAGE + row * A_PITCH + koff) * 2, gp, 16);
        }
#pragma unroll
        for (int i = 0; i < 2; i++) {
            int c = tid + i * 256;
            int drow = c >> 4;               // 0..31
            int voff = (c & 15) * 8;         // 0..120
            int v = bn * BN + voff;
            const __nv_bfloat16* gp = &g_w16[(size_t)(kt * BK + drow) * V_ + v];
            cp_async16(bs0 + (buf * B_STAGE + drow * B_PITCH + voff) * 2, gp, (v < V_) ? 16 : 0);
        }
        asm volatile("cp.async.commit_group;\n" ::: "memory");
    };

    load_tiles(0, 0);
    load_tiles(1, 1);

    if (tid < BM) {
        inv_x_s[tid]   = g_inv_x[bm * BM + tid];
        label_s[tid]   = g_labels[bm * BM + tid];
        int v = bn * BN + tid;
        inv_w_s[tid]   = (v < V_) ? g_inv_w[v] : 0.f;
        rowsum_sm[tid] = 0.f;
    }

    float acc[4][4][4];
#pragma unroll
    for (int mf = 0; mf < 4; mf++)
#pragma unroll
        for (int nf = 0; nf < 4; nf++)
#pragma unroll
            for (int j = 0; j < 4; j++) acc[mf][nf][j] = 0.f;

    const int KT = D_ / BK;  // 16
    for (int kt = 0; kt < KT; kt++) {
        asm volatile("cp.async.wait_group 1;\n" ::: "memory");
        __syncthreads();
        // prefetch kt+2 into the stage freed last iteration
        if (kt + 2 < KT) load_tiles(kt + 2, (kt + 2) % STAGES);
        else asm volatile("cp.async.commit_group;\n" ::: "memory");  // keep group count uniform

        int buf = kt % STAGES;
        uint32_t abase = as0 + buf * (A_STAGE * 2);
        uint32_t bbase = bs0 + buf * (B_STAGE * 2);

#pragma unroll
        for (int ks = 0; ks < 2; ks++) {
            uint32_t a[4][4];
#pragma unroll
            for (int mf = 0; mf < 4; mf++) {
                int row = wm * 64 + mf * 16 + (lane & 15);
                int col = ks * 16 + (lane >> 4) * 8;
                ldsm_x4(a[mf][0], a[mf][1], a[mf][2], a[mf][3],
                        abase + (row * A_PITCH + col) * 2);
            }
            uint32_t b[4][2];
#pragma unroll
            for (int ng = 0; ng < 2; ng++) {
                int krow = ks * 16 + (lane & 15);
                int ncol = wn * 32 + ng * 16 + (lane >> 4) * 8;
                uint32_t r0, r1, r2, r3;
                ldsm_x4_t(r0, r1, r2, r3, bbase + (krow * B_PITCH + ncol) * 2);
                b[ng * 2][0] = r0;      b[ng * 2][1] = r1;      // n 0..7 of group
                b[ng * 2 + 1][0] = r2;  b[ng * 2 + 1][1] = r3;  // n 8..15
            }
#pragma unroll
            for (int mf = 0; mf < 4; mf++)
#pragma unroll
                for (int nf = 0; nf < 4; nf++)
                    mma16816(acc[mf][nf], a[mf], b[nf]);
        }
    }
    __syncthreads();  // all compute done; rowsum_sm zeros visible

    // ---- fused ArcFace epilogue ----
#pragma unroll
    for (int mf = 0; mf < 4; mf++) {
        float rs0 = 0.f, rs1 = 0.f;
        int r0 = wm * 64 + mf * 16 + (lane >> 2);
        int r1 = r0 + 8;
#pragma unroll
        for (int nf = 0; nf < 4; nf++) {
            int cbase = wn * 32 + nf * 8 + (lane & 3) * 2;
#pragma unroll
            for (int j = 0; j < 2; j++) {
                int cc = cbase + j;
                int v = bn * BN + cc;
                if (v < V_) {
                    {
                        float cv = acc[mf][nf][j] * inv_x_s[r0] * inv_w_s[cc];
                        cv = fminf(fmaxf(cv, -1.f + EPS_CLIP), 1.f - EPS_CLIP);
                        float lg;
                        if (label_s[r0] == v) {
                            float s = sqrtf(fmaxf(1.f - cv * cv, 0.f));
                            lg = cv * MARGIN_COS - s * MARGIN_SIN;
                            g_label_logit[bm * BM + r0] = lg;
                        } else lg = cv;
                        rs0 += __expf(lg);
                    }
                    {
                        float cv = acc[mf][nf][2 + j] * inv_x_s[r1] * inv_w_s[cc];
                        cv = fminf(fmaxf(cv, -1.f + EPS_CLIP), 1.f - EPS_CLIP);
                        float lg;
                        if (label_s[r1] == v) {
                            float s = sqrtf(fmaxf(1.f - cv * cv, 0.f));
                            lg = cv * MARGIN_COS - s * MARGIN_SIN;
                            g_label_logit[bm * BM + r1] = lg;
                        } else lg = cv;
                        rs1 += __expf(lg);
                    }
                }
            }
        }
        rs0 += __shfl_xor_sync(0xffffffffu, rs0, 1);
        rs0 += __shfl_xor_sync(0xffffffffu, rs0, 2);
        rs1 += __shfl_xor_sync(0xffffffffu, rs1, 1);
        rs1 += __shfl_xor_sync(0xffffffffu, rs1, 2);
        if ((lane & 3) == 0) {
            atomicAdd(&rowsum_sm[r0], rs0);
            atomicAdd(&rowsum_sm[r1], rs1);
        }
    }
    __syncthreads();
    if (tid < BM) atomicAdd(&g_sumexp[bm * BM + tid], rowsum_sm[tid]);
}

// ============================================================
// final: loss = mean_b( log(sumexp[b]) - label_logit[b] )
// ============================================================
__global__ void k_final(float* __restrict__ out) {
    int t = threadIdx.x;  // 1024
    float v = logf(g_sumexp[t]) - g_label_logit[t];
#pragma unroll
    for (int o = 16; o; o >>= 1) v += __shfl_xor_sync(0xffffffffu, v, o);
    __shared__ float ws[32];
    if ((t & 31) == 0) ws[t >> 5] = v;
    __syncthreads();
    if (t < 32) {
        float s = ws[t];
#pragma unroll
        for (int o = 16; o; o >>= 1) s += __shfl_xor_sync(0xffffffffu, s, o);
        if (t == 0) out[0] = s * (1.0f / (float)B_);
    }
}

// ============================================================
extern "C" void kernel_launch(void* const* d_in, const int* in_sizes, int n_in,
                              void* d_out, int out_size) {
    const float* x = (const float*)d_in[0];
    const float* w = (const float*)d_in[1];
    const int*   labels_raw = (const int*)d_in[2];
    float* out = (float*)d_out;

    static bool attr_set = false;
    if (!attr_set) {
        cudaFuncSetAttribute(k_gemm, cudaFuncAttributeMaxDynamicSharedMemorySize, SMEM_DYN);
        attr_set = true;
    }

    k_labels<<<1, 1024>>>(labels_raw);
    k_prep_x<<<B_, 128>>>(x);
    k_prep_w<<<(V_ + 255) / 256, 256>>>(w);
    dim3 grid(B_ / BM, (V_ + BN - 1) / BN);  // (8, 782)
    k_gemm<<<grid, 256, SMEM_DYN>>>();
    k_final<<<1, 1024>>>(out);
}

// round 9
// speedup vs baseline: 1.0601x; 1.0044x over previous
#include <cuda_runtime.h>
#include <cuda_bf16.h>
#include <cstdint>

#define B_  1024
#define D_  512
#define V_  100000

constexpr float MARGIN_COS = 0.9210609940028851f;  // cos(0.4)
constexpr float MARGIN_SIN = 0.3894183423086505f;  // sin(0.4)
constexpr float EPS_CLIP   = 1e-7f;

// ---- scratch (device globals: allocation-free per harness rules) ----
__device__ __align__(128) __nv_bfloat16 g_x16[B_ * D_];
__device__ __align__(128) __nv_bfloat16 g_w16[(size_t)D_ * V_];
__device__ float g_inv_x[B_];
__device__ float g_inv_w[V_];
__device__ float g_sumexp[B_];
__device__ float g_label_logit[B_];
__device__ int   g_labels[B_];

// ============================================================
// labels dtype detection (int64 vs int32) + normalization
// ============================================================
__global__ void k_labels(const int* __restrict__ raw) {
    __shared__ int nonzero;
    int t = threadIdx.x;  // 1024
    if (t == 0) nonzero = 0;
    __syncthreads();
    if (t < 512) {
        if (raw[2 * t + 1] != 0) atomicOr(&nonzero, 1);
    }
    __syncthreads();
    bool is64 = (nonzero == 0);
    g_labels[t] = is64 ? raw[2 * t] : raw[t];
}

// ============================================================
// x prep: bf16 convert + row inv-norms; zero g_sumexp
// ============================================================
__global__ void k_prep_x(const float* __restrict__ x) {
    int b = blockIdx.x;
    int t = threadIdx.x;  // 128
    float ss = 0.f;
#pragma unroll
    for (int i = 0; i < 4; i++) {
        int k = t + i * 128;
        float v = x[b * D_ + k];
        ss += v * v;
        g_x16[b * D_ + k] = __float2bfloat16(v);
    }
#pragma unroll
    for (int o = 16; o; o >>= 1) ss += __shfl_xor_sync(0xffffffffu, ss, o);
    __shared__ float ws[4];
    if ((t & 31) == 0) ws[t >> 5] = ss;
    __syncthreads();
    if (t == 0) {
        float s = ws[0] + ws[1] + ws[2] + ws[3];
        g_inv_x[b]  = 1.0f / fmaxf(sqrtf(s), 1e-12f);
        g_sumexp[b] = 0.f;
    }
}

// ============================================================
// w prep: bf16 convert + column inv-norms (one pass, coalesced)
// ============================================================
__global__ void k_prep_w(const float* __restrict__ w) {
    int v = blockIdx.x * 256 + threadIdx.x;
    if (v >= V_) return;
    float ss = 0.f;
    size_t idx = (size_t)v;
#pragma unroll 8
    for (int d = 0; d < D_; d++) {
        float val = w[idx];
        ss += val * val;
        g_w16[idx] = __float2bfloat16(val);
        idx += V_;
    }
    g_inv_w[v] = 1.0f / fmaxf(sqrtf(ss), 1e-12f);
}

// ============================================================
// GEMM + fused ArcFace epilogue
// CTA: BM=128 x BN=128, BK=64, 512 threads (2x4 warp grid, 32x32/warp)
// 3-stage cp.async ring; mma.sync m16n8k16 bf16
// ============================================================
#define BM 128
#define BN 128
#define BK 64
#define STAGES 3
#define A_PITCH 72    // 64 + 8 pad (144B rows; r*144 mod 128 = r*16 -> conflict-free)
#define B_PITCH 136   // 128 + 8 pad (272B rows; conflict-free ldmatrix)
#define A_STAGE (BM * A_PITCH)          // bf16 elems
#define B_STAGE (BK * B_PITCH)
#define SMEM_DYN ((A_STAGE + B_STAGE) * STAGES * 2)  // 107520 bytes

__device__ __forceinline__ void cp_async16(uint32_t smem, const void* gmem, int sz) {
    asm volatile("cp.async.cg.shared.global [%0], [%1], 16, %2;\n"
                 :: "r"(smem), "l"(gmem), "r"(sz) : "memory");
}
__device__ __forceinline__ void ldsm_x4(uint32_t& r0, uint32_t& r1, uint32_t& r2, uint32_t& r3, uint32_t addr) {
    asm volatile("ldmatrix.sync.aligned.m8n8.x4.shared.b16 {%0,%1,%2,%3}, [%4];\n"
                 : "=r"(r0), "=r"(r1), "=r"(r2), "=r"(r3) : "r"(addr));
}
__device__ __forceinline__ void ldsm_x4_t(uint32_t& r0, uint32_t& r1, uint32_t& r2, uint32_t& r3, uint32_t addr) {
    asm volatile("ldmatrix.sync.aligned.m8n8.x4.trans.shared.b16 {%0,%1,%2,%3}, [%4];\n"
                 : "=r"(r0), "=r"(r1), "=r"(r2), "=r"(r3) : "r"(addr));
}
__device__ __forceinline__ void mma16816(float* c, const uint32_t* a, const uint32_t* b) {
    asm volatile(
        "mma.sync.aligned.m16n8k16.row.col.f32.bf16.bf16.f32 "
        "{%0,%1,%2,%3}, {%4,%5,%6,%7}, {%8,%9}, {%0,%1,%2,%3};\n"
        : "+f"(c[0]), "+f"(c[1]), "+f"(c[2]), "+f"(c[3])
        : "r"(a[0]), "r"(a[1]), "r"(a[2]), "r"(a[3]), "r"(b[0]), "r"(b[1]));
}

__global__ __launch_bounds__(512, 2) void k_gemm() {
    extern __shared__ __nv_bfloat16 smem_dyn[];
    __nv_bfloat16* As = smem_dyn;                       // STAGES * A_STAGE
    __nv_bfloat16* Bs = smem_dyn + STAGES * A_STAGE;    // STAGES * B_STAGE
    __shared__ float rowsum_sm[BM];
    __shared__ float inv_x_s[BM];
    __shared__ float inv_w_s[BN];
    __shared__ int   label_s[BM];

    const int bm = blockIdx.x;   // M-tile (fast index -> same-w CTAs adjacent for L2 reuse)
    const int bn = blockIdx.y;   // V-tile
    const int tid = threadIdx.x;
    const int warp = tid >> 5, lane = tid & 31;
    const int wm = warp & 3;     // 4 warps over M (32 rows each)
    const int wn = warp >> 2;    // 4 warps over N (32 cols each)

    const uint32_t as0 = (uint32_t)__cvta_generic_to_shared(As);
    const uint32_t bs0 = (uint32_t)__cvta_generic_to_shared(Bs);

    // 512 threads: A 16KB -> 2 cp16/thread; B 16KB -> 2 cp16/thread
    auto load_tiles = [&](int kt, int buf) {
#pragma unroll
        for (int i = 0; i < 2; i++) {
            int c = tid + i * 512;           // 0..1023
            int row  = c >> 3;               // 0..127
            int koff = (c & 7) * 8;          // 0..56
            const __nv_bfloat16* gp = &g_x16[(bm * BM + row) * D_ + kt * BK + koff];
            cp_async16(as0 + (buf * A_STAGE + row * A_PITCH + koff) * 2, gp, 16);
        }
#pragma unroll
        for (int i = 0; i < 2; i++) {
            int c = tid + i * 512;           // 0..1023
            int drow = c >> 4;               // 0..63
            int voff = (c & 15) * 8;         // 0..120
            int v = bn * BN + voff;
            const __nv_bfloat16* gp = &g_w16[(size_t)(kt * BK + drow) * V_ + v];
            cp_async16(bs0 + (buf * B_STAGE + drow * B_PITCH + voff) * 2, gp, (v < V_) ? 16 : 0);
        }
        asm volatile("cp.async.commit_group;\n" ::: "memory");
    };

    load_tiles(0, 0);
    load_tiles(1, 1);

    if (tid < BM) {
        inv_x_s[tid]   = g_inv_x[bm * BM + tid];
        label_s[tid]   = g_labels[bm * BM + tid];
        int v = bn * BN + tid;
        inv_w_s[tid]   = (v < V_) ? g_inv_w[v] : 0.f;
        rowsum_sm[tid] = 0.f;
    }

    float acc[2][4][4];
#pragma unroll
    for (int mf = 0; mf < 2; mf++)
#pragma unroll
        for (int nf = 0; nf < 4; nf++)
#pragma unroll
            for (int j = 0; j < 4; j++) acc[mf][nf][j] = 0.f;

    const int KT = D_ / BK;  // 8
    for (int kt = 0; kt < KT; kt++) {
        asm volatile("cp.async.wait_group 1;\n" ::: "memory");
        __syncthreads();
        // prefetch kt+2 into the stage freed last iteration
        if (kt + 2 < KT) load_tiles(kt + 2, (kt + 2) % STAGES);
        else asm volatile("cp.async.commit_group;\n" ::: "memory");  // keep group count uniform

        int buf = kt % STAGES;
        uint32_t abase = as0 + buf * (A_STAGE * 2);
        uint32_t bbase = bs0 + buf * (B_STAGE * 2);

#pragma unroll
        for (int ks = 0; ks < 4; ks++) {
            uint32_t a[2][4];
#pragma unroll
            for (int mf = 0; mf < 2; mf++) {
                int row = wm * 32 + mf * 16 + (lane & 15);
                int col = ks * 16 + (lane >> 4) * 8;
                ldsm_x4(a[mf][0], a[mf][1], a[mf][2], a[mf][3],
                        abase + (row * A_PITCH + col) * 2);
            }
            uint32_t b[4][2];
#pragma unroll
            for (int ng = 0; ng < 2; ng++) {
                int krow = ks * 16 + (lane & 15);
                int ncol = wn * 32 + ng * 16 + (lane >> 4) * 8;
                uint32_t r0, r1, r2, r3;
                ldsm_x4_t(r0, r1, r2, r3, bbase + (krow * B_PITCH + ncol) * 2);
                b[ng * 2][0] = r0;      b[ng * 2][1] = r1;      // n 0..7 of group
                b[ng * 2 + 1][0] = r2;  b[ng * 2 + 1][1] = r3;  // n 8..15
            }
#pragma unroll
            for (int mf = 0; mf < 2; mf++)
#pragma unroll
                for (int nf = 0; nf < 4; nf++)
                    mma16816(acc[mf][nf], a[mf], b[nf]);
        }
    }
    __syncthreads();  // all compute done; rowsum_sm zeros visible

    // ---- fused ArcFace epilogue ----
#pragma unroll
    for (int mf = 0; mf < 2; mf++) {
        float rs0 = 0.f, rs1 = 0.f;
        int r0 = wm * 32 + mf * 16 + (lane >> 2);
        int r1 = r0 + 8;
#pragma unroll
        for (int nf = 0; nf < 4; nf++) {
            int cbase = wn * 32 + nf * 8 + (lane & 3) * 2;
#pragma unroll
            for (int j = 0; j < 2; j++) {
                int cc = cbase + j;
                int v = bn * BN + cc;
                if (v < V_) {
                    {
                        float cv = acc[mf][nf][j] * inv_x_s[r0] * inv_w_s[cc];
                        cv = fminf(fmaxf(cv, -1.f + EPS_CLIP), 1.f - EPS_CLIP);
                        float lg;
                        if (label_s[r0] == v) {
                            float s = sqrtf(fmaxf(1.f - cv * cv, 0.f));
                            lg = cv * MARGIN_COS - s * MARGIN_SIN;
                            g_label_logit[bm * BM + r0] = lg;
                        } else lg = cv;
                        rs0 += __expf(lg);
                    }
                    {
                        float cv = acc[mf][nf][2 + j] * inv_x_s[r1] * inv_w_s[cc];
                        cv = fminf(fmaxf(cv, -1.f + EPS_CLIP), 1.f - EPS_CLIP);
                        float lg;
                        if (label_s[r1] == v) {
                            float s = sqrtf(fmaxf(1.f - cv * cv, 0.f));
                            lg = cv * MARGIN_COS - s * MARGIN_SIN;
                            g_label_logit[bm * BM + r1] = lg;
                        } else lg = cv;
                        rs1 += __expf(lg);
                    }
                }
            }
        }
        rs0 += __shfl_xor_sync(0xffffffffu, rs0, 1);
        rs0 += __shfl_xor_sync(0xffffffffu, rs0, 2);
        rs1 += __shfl_xor_sync(0xffffffffu, rs1, 1);
        rs1 += __shfl_xor_sync(0xffffffffu, rs1, 2);
        if ((lane & 3) == 0) {
            atomicAdd(&rowsum_sm[r0], rs0);
            atomicAdd(&rowsum_sm[r1], rs1);
        }
    }
    __syncthreads();
    if (tid < BM) atomicAdd(&g_sumexp[bm * BM + tid], rowsum_sm[tid]);
}

// ============================================================
// final: loss = mean_b( log(sumexp[b]) - label_logit[b] )
// ============================================================
__global__ void k_final(float* __restrict__ out) {
    int t = threadIdx.x;  // 1024
    float v = logf(g_sumexp[t]) - g_label_logit[t];
#pragma unroll
    for (int o = 16; o; o >>= 1) v += __shfl_xor_sync(0xffffffffu, v, o);
    __shared__ float ws[32];
    if ((t & 31) == 0) ws[t >> 5] = v;
    __syncthreads();
    if (t < 32) {
        float s = ws[t];
#pragma unroll
        for (int o = 16; o; o >>= 1) s += __shfl_xor_sync(0xffffffffu, s, o);
        if (t == 0) out[0] = s * (1.0f / (float)B_);
    }
}

// ============================================================
extern "C" void kernel_launch(void* const* d_in, const int* in_sizes, int n_in,
                              void* d_out, int out_size) {
    const float* x = (const float*)d_in[0];
    const float* w = (const float*)d_in[1];
    const int*   labels_raw = (const int*)d_in[2];
    float* out = (float*)d_out;

    static bool attr_set = false;
    if (!attr_set) {
        cudaFuncSetAttribute(k_gemm, cudaFuncAttributeMaxDynamicSharedMemorySize, SMEM_DYN);
        attr_set = true;
    }

    k_labels<<<1, 1024>>>(labels_raw);
    k_prep_x<<<B_, 128>>>(x);
    k_prep_w<<<(V_ + 255) / 256, 256>>>(w);
    dim3 grid(B_ / BM, (V_ + BN - 1) / BN);  // (8, 782)
    k_gemm<<<grid, 512, SMEM_DYN>>>();
    k_final<<<1, 1024>>>(out);
}

// round 10
// speedup vs baseline: 1.2516x; 1.1807x over previous
#include <cuda_runtime.h>
#include <cuda_bf16.h>
#include <cstdint>

#define B_  1024
#define D_  512
#define V_  100000

constexpr float MARGIN_COS = 0.9210609940028851f;  // cos(0.4)
constexpr float MARGIN_SIN = 0.3894183423086505f;  // sin(0.4)
constexpr float EPS_CLIP   = 1e-7f;

// ---- scratch (device globals: allocation-free per harness rules) ----
__device__ __align__(128) __nv_bfloat16 g_x16[B_ * D_];
__device__ __align__(128) __nv_bfloat16 g_w16[(size_t)D_ * V_];
__device__ float g_inv_x[B_];
__device__ float g_inv_w[V_];
__device__ float g_sumexp[B_];
__device__ float g_label_logit[B_];
__device__ int   g_labels[B_];

// ============================================================
// labels dtype detection (int64 vs int32) + normalization
// ============================================================
__global__ void k_labels(const int* __restrict__ raw) {
    __shared__ int nonzero;
    int t = threadIdx.x;  // 1024
    if (t == 0) nonzero = 0;
    __syncthreads();
    if (t < 512) {
        if (raw[2 * t + 1] != 0) atomicOr(&nonzero, 1);
    }
    __syncthreads();
    bool is64 = (nonzero == 0);
    g_labels[t] = is64 ? raw[2 * t] : raw[t];
}

// ============================================================
// x prep: bf16 convert + row inv-norms; zero g_sumexp
// ============================================================
__global__ void k_prep_x(const float* __restrict__ x) {
    int b = blockIdx.x;
    int t = threadIdx.x;  // 128
    float ss = 0.f;
#pragma unroll
    for (int i = 0; i < 4; i++) {
        int k = t + i * 128;
        float v = x[b * D_ + k];
        ss += v * v;
        g_x16[b * D_ + k] = __float2bfloat16(v);
    }
#pragma unroll
    for (int o = 16; o; o >>= 1) ss += __shfl_xor_sync(0xffffffffu, ss, o);
    __shared__ float ws[4];
    if ((t & 31) == 0) ws[t >> 5] = ss;
    __syncthreads();
    if (t == 0) {
        float s = ws[0] + ws[1] + ws[2] + ws[3];
        g_inv_x[b]  = 1.0f / fmaxf(sqrtf(s), 1e-12f);
        g_sumexp[b] = 0.f;
    }
}

// ============================================================
// w prep: bf16 convert + column inv-norms (one pass, coalesced)
// ============================================================
__global__ void k_prep_w(const float* __restrict__ w) {
    int v = blockIdx.x * 256 + threadIdx.x;
    if (v >= V_) return;
    float ss = 0.f;
    size_t idx = (size_t)v;
#pragma unroll 8
    for (int d = 0; d < D_; d++) {
        float val = w[idx];
        ss += val * val;
        g_w16[idx] = __float2bfloat16(val);
        idx += V_;
    }
    g_inv_w[v] = 1.0f / fmaxf(sqrtf(ss), 1e-12f);
}

// ============================================================
// GEMM + fused ArcFace epilogue
// CTA: BM=64 x BN=128, BK=32, 256 threads (2x4 warp grid, 32x32/warp)
// 4 CTAs/SM (barrier decorrelation); 3-stage cp.async ring
// ============================================================
#define BM 64
#define BN 128
#define BK 32
#define STAGES 3
#define A_PITCH 40    // 32 + 8 pad (80B rows; conflict-free ldmatrix)
#define B_PITCH 136   // 128 + 8 pad (272B rows; conflict-free ldmatrix)
#define A_STAGE (BM * A_PITCH)          // bf16 elems = 2560
#define B_STAGE (BK * B_PITCH)          // 4352
#define SMEM_DYN ((A_STAGE + B_STAGE) * STAGES * 2)  // 41472 bytes

__device__ __forceinline__ void cp_async16(uint32_t smem, const void* gmem, int sz) {
    asm volatile("cp.async.cg.shared.global [%0], [%1], 16, %2;\n"
                 :: "r"(smem), "l"(gmem), "r"(sz) : "memory");
}
__device__ __forceinline__ void ldsm_x4(uint32_t& r0, uint32_t& r1, uint32_t& r2, uint32_t& r3, uint32_t addr) {
    asm volatile("ldmatrix.sync.aligned.m8n8.x4.shared.b16 {%0,%1,%2,%3}, [%4];\n"
                 : "=r"(r0), "=r"(r1), "=r"(r2), "=r"(r3) : "r"(addr));
}
__device__ __forceinline__ void ldsm_x4_t(uint32_t& r0, uint32_t& r1, uint32_t& r2, uint32_t& r3, uint32_t addr) {
    asm volatile("ldmatrix.sync.aligned.m8n8.x4.trans.shared.b16 {%0,%1,%2,%3}, [%4];\n"
                 : "=r"(r0), "=r"(r1), "=r"(r2), "=r"(r3) : "r"(addr));
}
__device__ __forceinline__ void mma16816(float* c, const uint32_t* a, const uint32_t* b) {
    asm volatile(
        "mma.sync.aligned.m16n8k16.row.col.f32.bf16.bf16.f32 "
        "{%0,%1,%2,%3}, {%4,%5,%6,%7}, {%8,%9}, {%0,%1,%2,%3};\n"
        : "+f"(c[0]), "+f"(c[1]), "+f"(c[2]), "+f"(c[3])
        : "r"(a[0]), "r"(a[1]), "r"(a[2]), "r"(a[3]), "r"(b[0]), "r"(b[1]));
}

__global__ __launch_bounds__(256, 4) void k_gemm() {
    extern __shared__ __nv_bfloat16 smem_dyn[];
    __nv_bfloat16* As = smem_dyn;                       // STAGES * A_STAGE
    __nv_bfloat16* Bs = smem_dyn + STAGES * A_STAGE;    // STAGES * B_STAGE
    __shared__ float rowsum_sm[BM];
    __shared__ float inv_x_s[BM];
    __shared__ float inv_w_s[BN];
    __shared__ int   label_s[BM];

    const int bm = blockIdx.x;   // M-tile (fast index -> same-w CTAs adjacent for L2 reuse)
    const int bn = blockIdx.y;   // V-tile
    const int tid = threadIdx.x;
    const int warp = tid >> 5, lane = tid & 31;
    const int wm = warp & 1;     // 2 warps over M (32 rows each)
    const int wn = warp >> 1;    // 4 warps over N (32 cols each)

    const uint32_t as0 = (uint32_t)__cvta_generic_to_shared(As);
    const uint32_t bs0 = (uint32_t)__cvta_generic_to_shared(Bs);

    // 256 threads: A 4KB -> 1 cp16/thread; B 8KB -> 2 cp16/thread
    auto load_tiles = [&](int kt, int buf) {
        {
            int row  = tid >> 2;             // 0..63
            int koff = (tid & 3) * 8;        // 0,8,16,24
            const __nv_bfloat16* gp = &g_x16[(bm * BM + row) * D_ + kt * BK + koff];
            cp_async16(as0 + (buf * A_STAGE + row * A_PITCH + koff) * 2, gp, 16);
        }
#pragma unroll
        for (int i = 0; i < 2; i++) {
            int c = tid + i * 256;           // 0..511
            int drow = c >> 4;               // 0..31
            int voff = (c & 15) * 8;         // 0..120
            int v = bn * BN + voff;
            const __nv_bfloat16* gp = &g_w16[(size_t)(kt * BK + drow) * V_ + v];
            cp_async16(bs0 + (buf * B_STAGE + drow * B_PITCH + voff) * 2, gp, (v < V_) ? 16 : 0);
        }
        asm volatile("cp.async.commit_group;\n" ::: "memory");
    };

    load_tiles(0, 0);
    load_tiles(1, 1);

    if (tid < BM) {
        inv_x_s[tid]   = g_inv_x[bm * BM + tid];
        label_s[tid]   = g_labels[bm * BM + tid];
        rowsum_sm[tid] = 0.f;
    }
    if (tid < BN) {
        int v = bn * BN + tid;
        inv_w_s[tid]   = (v < V_) ? g_inv_w[v] : 0.f;
    }

    float acc[2][4][4];
#pragma unroll
    for (int mf = 0; mf < 2; mf++)
#pragma unroll
        for (int nf = 0; nf < 4; nf++)
#pragma unroll
            for (int j = 0; j < 4; j++) acc[mf][nf][j] = 0.f;

    const int KT = D_ / BK;  // 16
    for (int kt = 0; kt < KT; kt++) {
        asm volatile("cp.async.wait_group 1;\n" ::: "memory");
        __syncthreads();
        // prefetch kt+2 into the stage freed last iteration
        if (kt + 2 < KT) load_tiles(kt + 2, (kt + 2) % STAGES);
        else asm volatile("cp.async.commit_group;\n" ::: "memory");  // keep group count uniform

        int buf = kt % STAGES;
        uint32_t abase = as0 + buf * (A_STAGE * 2);
        uint32_t bbase = bs0 + buf * (B_STAGE * 2);

#pragma unroll
        for (int ks = 0; ks < 2; ks++) {
            uint32_t a[2][4];
#pragma unroll
            for (int mf = 0; mf < 2; mf++) {
                int row = wm * 32 + mf * 16 + (lane & 15);
                int col = ks * 16 + (lane >> 4) * 8;
                ldsm_x4(a[mf][0], a[mf][1], a[mf][2], a[mf][3],
                        abase + (row * A_PITCH + col) * 2);
            }
            uint32_t b[4][2];
#pragma unroll
            for (int ng = 0; ng < 2; ng++) {
                int krow = ks * 16 + (lane & 15);
                int ncol = wn * 32 + ng * 16 + (lane >> 4) * 8;
                uint32_t r0, r1, r2, r3;
                ldsm_x4_t(r0, r1, r2, r3, bbase + (krow * B_PITCH + ncol) * 2);
                b[ng * 2][0] = r0;      b[ng * 2][1] = r1;      // n 0..7 of group
                b[ng * 2 + 1][0] = r2;  b[ng * 2 + 1][1] = r3;  // n 8..15
            }
#pragma unroll
            for (int mf = 0; mf < 2; mf++)
#pragma unroll
                for (int nf = 0; nf < 4; nf++)
                    mma16816(acc[mf][nf], a[mf], b[nf]);
        }
    }
    __syncthreads();  // all compute done; rowsum_sm zeros visible

    // ---- fused ArcFace epilogue ----
#pragma unroll
    for (int mf = 0; mf < 2; mf++) {
        float rs0 = 0.f, rs1 = 0.f;
        int r0 = wm * 32 + mf * 16 + (lane >> 2);
        int r1 = r0 + 8;
#pragma unroll
        for (int nf = 0; nf < 4; nf++) {
            int cbase = wn * 32 + nf * 8 + (lane & 3) * 2;
#pragma unroll
            for (int j = 0; j < 2; j++) {
                int cc = cbase + j;
                int v = bn * BN + cc;
                if (v < V_) {
                    {
                        float cv = acc[mf][nf][j] * inv_x_s[r0] * inv_w_s[cc];
                        cv = fminf(fmaxf(cv, -1.f + EPS_CLIP), 1.f - EPS_CLIP);
                        float lg;
                        if (label_s[r0] == v) {
                            float s = sqrtf(fmaxf(1.f - cv * cv, 0.f));
                            lg = cv * MARGIN_COS - s * MARGIN_SIN;
                            g_label_logit[bm * BM + r0] = lg;
                        } else lg = cv;
                        rs0 += __expf(lg);
                    }
                    {
                        float cv = acc[mf][nf][2 + j] * inv_x_s[r1] * inv_w_s[cc];
                        cv = fminf(fmaxf(cv, -1.f + EPS_CLIP), 1.f - EPS_CLIP);
                        float lg;
                        if (label_s[r1] == v) {
                            float s = sqrtf(fmaxf(1.f - cv * cv, 0.f));
                            lg = cv * MARGIN_COS - s * MARGIN_SIN;
                            g_label_logit[bm * BM + r1] = lg;
                        } else lg = cv;
                        rs1 += __expf(lg);
                    }
                }
            }
        }
        rs0 += __shfl_xor_sync(0xffffffffu, rs0, 1);
        rs0 += __shfl_xor_sync(0xffffffffu, rs0, 2);
        rs1 += __shfl_xor_sync(0xffffffffu, rs1, 1);
        rs1 += __shfl_xor_sync(0xffffffffu, rs1, 2);
        if ((lane & 3) == 0) {
            atomicAdd(&rowsum_sm[r0], rs0);
            atomicAdd(&rowsum_sm[r1], rs1);
        }
    }
    __syncthreads();
    if (tid < BM) atomicAdd(&g_sumexp[bm * BM + tid], rowsum_sm[tid]);
}

// ============================================================
// final: loss = mean_b( log(sumexp[b]) - label_logit[b] )
// ============================================================
__global__ void k_final(float* __restrict__ out) {
    int t = threadIdx.x;  // 1024
    float v = logf(g_sumexp[t]) - g_label_logit[t];
#pragma unroll
    for (int o = 16; o; o >>= 1) v += __shfl_xor_sync(0xffffffffu, v, o);
    __shared__ float ws[32];
    if ((t & 31) == 0) ws[t >> 5] = v;
    __syncthreads();
    if (t < 32) {
        float s = ws[t];
#pragma unroll
        for (int o = 16; o; o >>= 1) s += __shfl_xor_sync(0xffffffffu, s, o);
        if (t == 0) out[0] = s * (1.0f / (float)B_);
    }
}

// ============================================================
extern "C" void kernel_launch(void* const* d_in, const int* in_sizes, int n_in,
                              void* d_out, int out_size) {
    const float* x = (const float*)d_in[0];
    const float* w = (const float*)d_in[1];
    const int*   labels_raw = (const int*)d_in[2];
    float* out = (float*)d_out;

    static bool attr_set = false;
    if (!attr_set) {
        cudaFuncSetAttribute(k_gemm, cudaFuncAttributeMaxDynamicSharedMemorySize, SMEM_DYN);
        attr_set = true;
    }

    k_labels<<<1, 1024>>>(labels_raw);
    k_prep_x<<<B_, 128>>>(x);
    k_prep_w<<<(V_ + 255) / 256, 256>>>(w);
    dim3 grid(B_ / BM, (V_ + BN - 1) / BN);  // (16, 782)
    k_gemm<<<grid, 256, SMEM_DYN>>>();
    k_final<<<1, 1024>>>(out);
}

// round 11
// speedup vs baseline: 1.2865x; 1.0279x over previous
#include <cuda_runtime.h>
#include <cuda_fp16.h>
#include <cstdint>

#define B_  1024
#define D_  512
#define V_  100000

constexpr float MARGIN_COS = 0.9210609940028851f;  // cos(0.4)
constexpr float MARGIN_SIN = 0.3894183423086505f;  // sin(0.4)
constexpr float EPS_CLIP   = 1e-7f;

// ---- scratch (device globals: allocation-free per harness rules) ----
__device__ __align__(128) __half g_x16[B_ * D_];
__device__ __align__(128) __half g_w16[(size_t)D_ * V_];
__device__ float g_inv_x[B_];
__device__ float g_inv_w[V_];
__device__ float g_sumexp[B_];
__device__ float g_label_logit[B_];
__device__ int   g_labels[B_];

// ============================================================
// labels dtype detection (int64 vs int32) + normalization
// ============================================================
__global__ void k_labels(const int* __restrict__ raw) {
    __shared__ int nonzero;
    int t = threadIdx.x;  // 1024
    if (t == 0) nonzero = 0;
    __syncthreads();
    if (t < 512) {
        if (raw[2 * t + 1] != 0) atomicOr(&nonzero, 1);
    }
    __syncthreads();
    bool is64 = (nonzero == 0);
    g_labels[t] = is64 ? raw[2 * t] : raw[t];
}

// ============================================================
// x prep: fp16 convert + row inv-norms; zero g_sumexp
// ============================================================
__global__ void k_prep_x(const float* __restrict__ x) {
    int b = blockIdx.x;
    int t = threadIdx.x;  // 128
    float ss = 0.f;
#pragma unroll
    for (int i = 0; i < 4; i++) {
        int k = t + i * 128;
        float v = x[b * D_ + k];
        ss += v * v;
        g_x16[b * D_ + k] = __float2half(v);
    }
#pragma unroll
    for (int o = 16; o; o >>= 1) ss += __shfl_xor_sync(0xffffffffu, ss, o);
    __shared__ float ws[4];
    if ((t & 31) == 0) ws[t >> 5] = ss;
    __syncthreads();
    if (t == 0) {
        float s = ws[0] + ws[1] + ws[2] + ws[3];
        g_inv_x[b]  = 1.0f / fmaxf(sqrtf(s), 1e-12f);
        g_sumexp[b] = 0.f;
    }
}

// ============================================================
// w prep: fp16 convert + column inv-norms (one pass, coalesced)
// ============================================================
__global__ void k_prep_w(const float* __restrict__ w) {
    int v = blockIdx.x * 256 + threadIdx.x;
    if (v >= V_) return;
    float ss = 0.f;
    size_t idx = (size_t)v;
#pragma unroll 8
    for (int d = 0; d < D_; d++) {
        float val = w[idx];
        ss += val * val;
        g_w16[idx] = __float2half(val);
        idx += V_;
    }
    g_inv_w[v] = 1.0f / fmaxf(sqrtf(ss), 1e-12f);
}

// ============================================================
// GEMM + fused ArcFace epilogue  (fp16 inputs, fp16 accum)
// CTA: BM=128 x BN=256, BK=32, 512 threads (2x8 warp grid, 64x32/warp)
// 2 CTAs/SM; 3-stage cp.async ring; mma.sync m16n8k16 f16
// ============================================================
#define BM 128
#define BN 256
#define BK 32
#define STAGES 3
#define A_PITCH 40    // 32 + 8 pad (80B rows; conflict-free ldmatrix)
#define B_PITCH 264   // 256 + 8 pad (528B rows; 528 mod 128 = 16 -> conflict-free)
#define A_STAGE (BM * A_PITCH)          // halves = 5120
#define B_STAGE (BK * B_PITCH)          // 8448
#define SMEM_DYN ((A_STAGE + B_STAGE) * STAGES * 2)  // 81408 bytes

__device__ __forceinline__ void cp_async16(uint32_t smem, const void* gmem, int sz) {
    asm volatile("cp.async.cg.shared.global [%0], [%1], 16, %2;\n"
                 :: "r"(smem), "l"(gmem), "r"(sz) : "memory");
}
__device__ __forceinline__ void ldsm_x4(uint32_t& r0, uint32_t& r1, uint32_t& r2, uint32_t& r3, uint32_t addr) {
    asm volatile("ldmatrix.sync.aligned.m8n8.x4.shared.b16 {%0,%1,%2,%3}, [%4];\n"
                 : "=r"(r0), "=r"(r1), "=r"(r2), "=r"(r3) : "r"(addr));
}
__device__ __forceinline__ void ldsm_x4_t(uint32_t& r0, uint32_t& r1, uint32_t& r2, uint32_t& r3, uint32_t addr) {
    asm volatile("ldmatrix.sync.aligned.m8n8.x4.trans.shared.b16 {%0,%1,%2,%3}, [%4];\n"
                 : "=r"(r0), "=r"(r1), "=r"(r2), "=r"(r3) : "r"(addr));
}
// fp16-accumulate MMA: D,C are 2 regs (half2 each)
__device__ __forceinline__ void mma16816_f16(uint32_t* c, const uint32_t* a, const uint32_t* b) {
    asm volatile(
        "mma.sync.aligned.m16n8k16.row.col.f16.f16.f16.f16 "
        "{%0,%1}, {%2,%3,%4,%5}, {%6,%7}, {%0,%1};\n"
        : "+r"(c[0]), "+r"(c[1])
        : "r"(a[0]), "r"(a[1]), "r"(a[2]), "r"(a[3]), "r"(b[0]), "r"(b[1]));
}

__global__ __launch_bounds__(512, 2) void k_gemm() {
    extern __shared__ __half smem_dyn[];
    __half* As = smem_dyn;                       // STAGES * A_STAGE
    __half* Bs = smem_dyn + STAGES * A_STAGE;    // STAGES * B_STAGE
    __shared__ float rowsum_sm[BM];
    __shared__ float inv_x_s[BM];
    __shared__ float inv_w_s[BN];
    __shared__ int   label_s[BM];

    const int bm = blockIdx.x;   // M-tile (fast index -> same-w CTAs adjacent for L2 reuse)
    const int bn = blockIdx.y;   // V-tile
    const int tid = threadIdx.x;
    const int warp = tid >> 5, lane = tid & 31;
    const int wm = warp & 1;     // 2 warps over M (64 rows each)
    const int wn = warp >> 1;    // 8 warps over N (32 cols each)

    const uint32_t as0 = (uint32_t)__cvta_generic_to_shared(As);
    const uint32_t bs0 = (uint32_t)__cvta_generic_to_shared(Bs);

    // 512 threads: A 8KB -> 1 cp16/thread; B 16KB -> 2 cp16/thread
    auto load_tiles = [&](int kt, int buf) {
        {
            int row  = tid >> 2;             // 0..127
            int koff = (tid & 3) * 8;        // 0,8,16,24
            const __half* gp = &g_x16[(bm * BM + row) * D_ + kt * BK + koff];
            cp_async16(as0 + (buf * A_STAGE + row * A_PITCH + koff) * 2, gp, 16);
        }
#pragma unroll
        for (int i = 0; i < 2; i++) {
            int c = tid + i * 512;           // 0..1023
            int drow = c >> 5;               // 0..31
            int voff = (c & 31) * 8;         // 0..248
            int v = bn * BN + voff;
            const __half* gp = &g_w16[(size_t)(kt * BK + drow) * V_ + v];
            cp_async16(bs0 + (buf * B_STAGE + drow * B_PITCH + voff) * 2, gp, (v < V_) ? 16 : 0);
        }
        asm volatile("cp.async.commit_group;\n" ::: "memory");
    };

    load_tiles(0, 0);
    load_tiles(1, 1);

    if (tid < BM) {
        inv_x_s[tid]   = g_inv_x[bm * BM + tid];
        label_s[tid]   = g_labels[bm * BM + tid];
        rowsum_sm[tid] = 0.f;
    }
    if (tid < BN) {
        int v = bn * BN + tid;
        inv_w_s[tid]   = (v < V_) ? g_inv_w[v] : 0.f;
    }

    uint32_t acc[4][4][2];  // fp16 accumulators (half2 pairs), rows mf, col-groups nf
#pragma unroll
    for (int mf = 0; mf < 4; mf++)
#pragma unroll
        for (int nf = 0; nf < 4; nf++) {
            acc[mf][nf][0] = 0u;
            acc[mf][nf][1] = 0u;
        }

    const int KT = D_ / BK;  // 16
    for (int kt = 0; kt < KT; kt++) {
        asm volatile("cp.async.wait_group 1;\n" ::: "memory");
        __syncthreads();
        // prefetch kt+2 into the stage freed last iteration
        if (kt + 2 < KT) load_tiles(kt + 2, (kt + 2) % STAGES);
        else asm volatile("cp.async.commit_group;\n" ::: "memory");  // keep group count uniform

        int buf = kt % STAGES;
        uint32_t abase = as0 + buf * (A_STAGE * 2);
        uint32_t bbase = bs0 + buf * (B_STAGE * 2);

#pragma unroll
        for (int ks = 0; ks < 2; ks++) {
            uint32_t a[4][4];
#pragma unroll
            for (int mf = 0; mf < 4; mf++) {
                int row = wm * 64 + mf * 16 + (lane & 15);
                int col = ks * 16 + (lane >> 4) * 8;
                ldsm_x4(a[mf][0], a[mf][1], a[mf][2], a[mf][3],
                        abase + (row * A_PITCH + col) * 2);
            }
            uint32_t b[4][2];
#pragma unroll
            for (int ng = 0; ng < 2; ng++) {
                int krow = ks * 16 + (lane & 15);
                int ncol = wn * 32 + ng * 16 + (lane >> 4) * 8;
                uint32_t r0, r1, r2, r3;
                ldsm_x4_t(r0, r1, r2, r3, bbase + (krow * B_PITCH + ncol) * 2);
                b[ng * 2][0] = r0;      b[ng * 2][1] = r1;      // n 0..7 of group
                b[ng * 2 + 1][0] = r2;  b[ng * 2 + 1][1] = r3;  // n 8..15
            }
#pragma unroll
            for (int mf = 0; mf < 4; mf++)
#pragma unroll
                for (int nf = 0; nf < 4; nf++)
                    mma16816_f16(acc[mf][nf], a[mf], b[nf]);
        }
    }
    __syncthreads();  // all compute done; rowsum_sm zeros visible

    // ---- fused ArcFace epilogue ----
#pragma unroll
    for (int mf = 0; mf < 4; mf++) {
        float rs0 = 0.f, rs1 = 0.f;
        int r0 = wm * 64 + mf * 16 + (lane >> 2);
        int r1 = r0 + 8;
#pragma unroll
        for (int nf = 0; nf < 4; nf++) {
            int cbase = wn * 32 + nf * 8 + (lane & 3) * 2;
            float2 v0 = __half22float2(*reinterpret_cast<__half2*>(&acc[mf][nf][0]));  // row r0
            float2 v1 = __half22float2(*reinterpret_cast<__half2*>(&acc[mf][nf][1]));  // row r1
            float d0[2] = {v0.x, v0.y};
            float d1[2] = {v1.x, v1.y};
#pragma unroll
            for (int j = 0; j < 2; j++) {
                int cc = cbase + j;
                int v = bn * BN + cc;
                if (v < V_) {
                    {
                        float cv = d0[j] * inv_x_s[r0] * inv_w_s[cc];
                        cv = fminf(fmaxf(cv, -1.f + EPS_CLIP), 1.f - EPS_CLIP);
                        float lg;
                        if (label_s[r0] == v) {
                            float s = sqrtf(fmaxf(1.f - cv * cv, 0.f));
                            lg = cv * MARGIN_COS - s * MARGIN_SIN;
                            g_label_logit[bm * BM + r0] = lg;
                        } else lg = cv;
                        rs0 += __expf(lg);
                    }
                    {
                        float cv = d1[j] * inv_x_s[r1] * inv_w_s[cc];
                        cv = fminf(fmaxf(cv, -1.f + EPS_CLIP), 1.f - EPS_CLIP);
                        float lg;
                        if (label_s[r1] == v) {
                            float s = sqrtf(fmaxf(1.f - cv * cv, 0.f));
                            lg = cv * MARGIN_COS - s * MARGIN_SIN;
                            g_label_logit[bm * BM + r1] = lg;
                        } else lg = cv;
                        rs1 += __expf(lg);
                    }
                }
            }
        }
        rs0 += __shfl_xor_sync(0xffffffffu, rs0, 1);
        rs0 += __shfl_xor_sync(0xffffffffu, rs0, 2);
        rs1 += __shfl_xor_sync(0xffffffffu, rs1, 1);
        rs1 += __shfl_xor_sync(0xffffffffu, rs1, 2);
        if ((lane & 3) == 0) {
            atomicAdd(&rowsum_sm[r0], rs0);
            atomicAdd(&rowsum_sm[r1], rs1);
        }
    }
    __syncthreads();
    if (tid < BM) atomicAdd(&g_sumexp[bm * BM + tid], rowsum_sm[tid]);
}

// ============================================================
// final: loss = mean_b( log(sumexp[b]) - label_logit[b] )
// ============================================================
__global__ void k_final(float* __restrict__ out) {
    int t = threadIdx.x;  // 1024
    float v = logf(g_sumexp[t]) - g_label_logit[t];
#pragma unroll
    for (int o = 16; o; o >>= 1) v += __shfl_xor_sync(0xffffffffu, v, o);
    __shared__ float ws[32];
    if ((t & 31) == 0) ws[t >> 5] = v;
    __syncthreads();
    if (t < 32) {
        float s = ws[t];
#pragma unroll
        for (int o = 16; o; o >>= 1) s += __shfl_xor_sync(0xffffffffu, s, o);
        if (t == 0) out[0] = s * (1.0f / (float)B_);
    }
}

// ============================================================
extern "C" void kernel_launch(void* const* d_in, const int* in_sizes, int n_in,
                              void* d_out, int out_size) {
    const float* x = (const float*)d_in[0];
    const float* w = (const float*)d_in[1];
    const int*   labels_raw = (const int*)d_in[2];
    float* out = (float*)d_out;

    static bool attr_set = false;
    if (!attr_set) {
        cudaFuncSetAttribute(k_gemm, cudaFuncAttributeMaxDynamicSharedMemorySize, SMEM_DYN);
        attr_set = true;
    }

    k_labels<<<1, 1024>>>(labels_raw);
    k_prep_x<<<B_, 128>>>(x);
    k_prep_w<<<(V_ + 255) / 256, 256>>>(w);
    dim3 grid(B_ / BM, (V_ + BN - 1) / BN);  // (8, 391)
    k_gemm<<<grid, 512, SMEM_DYN>>>();
    k_final<<<1, 1024>>>(out);
}